// round 2
// baseline (speedup 1.0000x reference)
#include <cuda_runtime.h>
#include <cuda_bf16.h>
#include <math.h>

// BlockGCN fused kernel, round 2: f32x2 packed FMA, 2 timesteps/thread.
// out = relu( BN( sum_k conv_k( einsum(x, BnA_k) ) ) + x )
// x (32,128,256,23), K=3, H=8, cin_g=cout_g=16, V=23.

#define NK 3
#define NH 8
#define NV 23
#define NVP 24
#define CG 16
#define NT 256
#define NN 32
#define NC 128
#define TB 16           // timesteps per block (8 t-pairs)
#define T2B 8           // t-pairs per block
#define THREADS 192     // 8*23=184 active in compute

typedef unsigned long long ull;

__device__ __forceinline__ ull fma2(ull a, ull b, ull c) {
    ull d;
    asm("fma.rn.f32x2 %0, %1, %2, %3;" : "=l"(d) : "l"(a), "l"(b), "l"(c));
    return d;
}
__device__ __forceinline__ ull add2(ull a, ull b) {
    ull d;
    asm("add.rn.f32x2 %0, %1, %2;" : "=l"(d) : "l"(a), "l"(b));
    return d;
}
__device__ __forceinline__ ull pack2(float lo, float hi) {
    ull d;
    asm("mov.b64 %0, {%1, %2};" : "=l"(d) : "f"(lo), "f"(hi));
    return d;
}
__device__ __forceinline__ void unpack2(ull v, float& lo, float& hi) {
    asm("mov.b64 {%0, %1}, %2;" : "=f"(lo), "=f"(hi) : "l"(v));
}

// Precomputed small tensors (device globals; no allocation).
__device__ float g_bna[NK][NH][NVP][NVP];  // [k][h][v][w], zero padded
__device__ float g_ws[NK][NH][CG][CG];     // [k][h][c][o]  (BN-scale folded, transposed)
__device__ float g_bias[NC];               // folded bias

__global__ void precompute_kernel(const float* __restrict__ emb,
                                  const float* __restrict__ A,
                                  const float* __restrict__ conv_w,
                                  const float* __restrict__ conv_b,
                                  const float* __restrict__ gamma,
                                  const float* __restrict__ beta,
                                  const float* __restrict__ mean,
                                  const float* __restrict__ var,
                                  const int*   __restrict__ hop,
                                  int n_hop)
{
    int b = blockIdx.x;
    int tid = threadIdx.x;
    if (b < NK * NH) {
        int k = b / NH, h = b % NH;
        // zero the padded 24x24 block
        for (int i = tid; i < NVP * NVP; i += blockDim.x)
            g_bna[k][h][i / NVP][i % NVP] = 0.f;
        __syncthreads();
        int w = tid;
        if (w < NV) {
            float Bc[NV], Ac[NV];
            float sB = 0.f, sA = 0.f;
            #pragma unroll
            for (int v = 0; v < NV; v++) {
                float bb = emb[(k * NH + h) * n_hop + hop[v * NV + w]];
                float aa = A[((k * NH + h) * NV + v) * NV + w];
                Bc[v] = bb; Ac[v] = aa;
                sB += bb * bb; sA += aa * aa;
            }
            float iB = 1.f / (sqrtf(sB) + 1e-4f);
            float iA = 1.f / (sqrtf(sA) + 1e-4f);
            #pragma unroll
            for (int v = 0; v < NV; v++)
                g_bna[k][h][v][w] = Bc[v] * iB + Ac[v] * iA;
        }
    } else {
        // Folded weights, transposed: g_ws[k][h][c][o] = conv_w[(k*128+h*16+o)*16+c] * inv[och]
        for (int idx = tid; idx < NK * NC * CG; idx += blockDim.x) {
            int row = idx / CG, c = idx % CG;
            int k = row / NC, och = row % NC;
            float inv = gamma[och] * rsqrtf(var[och] + 1e-5f);
            int h = och / CG, o = och % CG;
            g_ws[k][h][c][o] = conv_w[row * CG + c] * inv;
        }
        for (int och = tid; och < NC; och += blockDim.x) {
            float inv = gamma[och] * rsqrtf(var[och] + 1e-5f);
            float sb = conv_b[och] + conv_b[NC + och] + conv_b[2 * NC + och];
            g_bias[och] = sb * inv + beta[och] - mean[och] * inv;
        }
    }
}

// smem x tile: [t2][v][c] pairs, c row padded 16->18 pairs (144B) to break
// bank-phase alignment for the residual read. Stored as floats (2 per pair).
#define CPAD 18

__global__ __launch_bounds__(THREADS, 4)
void blockgcn_main_kernel(const float* __restrict__ x, float* __restrict__ out)
{
    __shared__ __align__(16) float xs[T2B * NVP * CPAD * 2];     // 27648 B
    __shared__ __align__(16) float bnas[NK * NVP * NVP];          //  6912 B
    __shared__ __align__(16) float ws2f[NK * CG * CG * 2];        //  6144 B
    __shared__ __align__(16) float bias2f[CG * 2];

    const int tile = blockIdx.x;   // 0..15
    const int n    = blockIdx.y;   // 0..31
    const int h    = blockIdx.z;   // 0..7
    const int t0   = tile * TB;
    const int tid  = threadIdx.x;

    // ---- stage x tile: transpose to [t2][v][c-pair] ----
    const float* xbase = x + ((size_t)(n * NC + h * CG)) * (NT * NV) + (size_t)t0 * NV;
    for (int idx = tid; idx < CG * TB * NV; idx += THREADS) {
        int c = idx / (TB * NV);
        int r = idx % (TB * NV);
        int t = r / NV, v = r % NV;
        float val = xbase[(size_t)c * (NT * NV) + r];
        xs[((t >> 1) * NVP + v) * (CPAD * 2) + c * 2 + (t & 1)] = val;
    }
    // ---- stage BnA for this h ----
    for (int idx = tid; idx < NK * NVP * NVP; idx += THREADS) {
        int k = idx / (NVP * NVP), rem = idx % (NVP * NVP);
        bnas[idx] = (&g_bna[k][h][0][0])[rem];
    }
    // ---- stage duplicated weights ----
    for (int idx = tid; idx < NK * CG * CG; idx += THREADS) {
        int k = idx / (CG * CG), rem = idx % (CG * CG);
        float v = (&g_ws[k][h][0][0])[rem];
        ws2f[idx * 2]     = v;
        ws2f[idx * 2 + 1] = v;
    }
    if (tid < CG) {
        float bv = g_bias[h * CG + tid];
        bias2f[tid * 2]     = bv;
        bias2f[tid * 2 + 1] = bv;
    }
    __syncthreads();

    if (tid < T2B * NV) {
        const int t2 = tid / NV;
        const int w  = tid % NV;

        // init: residual + folded bias
        ull acc2[CG];
        {
            const ulonglong2* xr = (const ulonglong2*)&xs[(t2 * NVP + w) * (CPAD * 2)];
            const ulonglong2* bp = (const ulonglong2*)bias2f;
            #pragma unroll
            for (int q = 0; q < 8; q++) {
                ulonglong2 u = xr[q];
                ulonglong2 b = bp[q];
                acc2[2 * q]     = add2(u.x, b.x);
                acc2[2 * q + 1] = add2(u.y, b.y);
            }
        }

        #pragma unroll 1
        for (int k = 0; k < NK; k++) {
            // adjacency: tmp2[c] = sum_v x2[c,t-pair,v] * BnA_k[v,w]
            ull tmp2[CG];
            #pragma unroll
            for (int c = 0; c < CG; c++) tmp2[c] = 0ull;

            const float* bcolp = &bnas[k * NVP * NVP + w];
            #pragma unroll
            for (int v = 0; v < NV; v++) {
                float bv = bcolp[v * NVP];
                ull bv2 = pack2(bv, bv);
                const ulonglong2* xp = (const ulonglong2*)&xs[(t2 * NVP + v) * (CPAD * 2)];
                #pragma unroll
                for (int q = 0; q < 8; q++) {
                    ulonglong2 u = xp[q];
                    tmp2[2 * q]     = fma2(u.x, bv2, tmp2[2 * q]);
                    tmp2[2 * q + 1] = fma2(u.y, bv2, tmp2[2 * q + 1]);
                }
            }
            // channel mix (BN folded): acc2[o] += tmp2[c] * ws[k][c][o]
            #pragma unroll
            for (int c = 0; c < CG; c++) {
                const ulonglong2* wp = (const ulonglong2*)&ws2f[(k * CG + c) * CG * 2];
                ull t = tmp2[c];
                #pragma unroll
                for (int q = 0; q < 8; q++) {
                    ulonglong2 uw = wp[q];
                    acc2[2 * q]     = fma2(t, uw.x, acc2[2 * q]);
                    acc2[2 * q + 1] = fma2(t, uw.y, acc2[2 * q + 1]);
                }
            }
        }

        // epilogue: relu + store both timesteps
        float* ob = out + ((size_t)(n * NC + h * CG)) * (NT * NV)
                        + (size_t)(t0 + 2 * t2) * NV + w;
        #pragma unroll
        for (int o = 0; o < CG; o++) {
            float a, b;
            unpack2(acc2[o], a, b);
            ob[(size_t)o * (NT * NV)]      = fmaxf(a, 0.f);
            ob[(size_t)o * (NT * NV) + NV] = fmaxf(b, 0.f);
        }
    }
}

extern "C" void kernel_launch(void* const* d_in, const int* in_sizes, int n_in,
                              void* d_out, int out_size)
{
    const float* x      = (const float*)d_in[0];
    const float* emb    = (const float*)d_in[1];
    const float* A      = (const float*)d_in[2];
    const float* conv_w = (const float*)d_in[3];
    const float* conv_b = (const float*)d_in[4];
    const float* gamma  = (const float*)d_in[5];
    const float* beta   = (const float*)d_in[6];
    const float* mean   = (const float*)d_in[7];
    const float* var    = (const float*)d_in[8];
    const int*   hop    = (const int*)d_in[9];

    int n_hop = in_sizes[1] / (NK * NH);

    precompute_kernel<<<NK * NH + 1, 256>>>(emb, A, conv_w, conv_b,
                                            gamma, beta, mean, var, hop, n_hop);

    dim3 grid(NT / TB, NN, NH);
    blockgcn_main_kernel<<<grid, THREADS>>>(x, (float*)d_out);
}

// round 3
// speedup vs baseline: 5.7289x; 5.7289x over previous
#include <cuda_runtime.h>
#include <cuda_bf16.h>
#include <math.h>

// BlockGCN fused kernel, round 3: spill-free SIMT, o-pair f32x2 accumulators.
// out = relu( BN( sum_k conv_k( einsum(x, BnA_k) ) ) + x )
// x (32,128,256,23), K=3, H=8, cin_g=cout_g=16, V=23.

#define NK 3
#define NH 8
#define NV 23
#define NVP 24
#define CG 16
#define NT 256
#define NN 32
#define NC 128
#define TB 16            // timesteps per block
#define THREADS 368      // 16 t x 23 w

typedef unsigned long long ull;

__device__ __forceinline__ ull fma2(ull a, ull b, ull c) {
    ull d;
    asm("fma.rn.f32x2 %0, %1, %2, %3;" : "=l"(d) : "l"(a), "l"(b), "l"(c));
    return d;
}
__device__ __forceinline__ ull pack2(float lo, float hi) {
    ull d;
    asm("mov.b64 %0, {%1, %2};" : "=l"(d) : "f"(lo), "f"(hi));
    return d;
}
__device__ __forceinline__ void unpack2(ull v, float& lo, float& hi) {
    asm("mov.b64 {%0, %1}, %2;" : "=f"(lo), "=f"(hi) : "l"(v));
}

// Precomputed small tensors (device globals; no allocation).
__device__ float g_bna[NK][NH][NV][NVP];   // [k][h][w][v], v padded with 0
__device__ float g_ws[NK][NH][CG][CG];     // [k][h][c][o]  (BN folded, o contiguous)
__device__ float g_bias[NC];               // folded bias

__global__ void precompute_kernel(const float* __restrict__ emb,
                                  const float* __restrict__ A,
                                  const float* __restrict__ conv_w,
                                  const float* __restrict__ conv_b,
                                  const float* __restrict__ gamma,
                                  const float* __restrict__ beta,
                                  const float* __restrict__ mean,
                                  const float* __restrict__ var,
                                  const int*   __restrict__ hop,
                                  int n_hop)
{
    int b = blockIdx.x;
    int tid = threadIdx.x;
    if (b < NK * NH) {
        int k = b / NH, h = b % NH;
        int w = tid;
        if (w < NV) {
            float Bc[NV], Ac[NV];
            float sB = 0.f, sA = 0.f;
            #pragma unroll
            for (int v = 0; v < NV; v++) {
                float bb = emb[(k * NH + h) * n_hop + hop[v * NV + w]];
                float aa = A[((k * NH + h) * NV + v) * NV + w];
                Bc[v] = bb; Ac[v] = aa;
                sB += bb * bb; sA += aa * aa;
            }
            float iB = 1.f / (sqrtf(sB) + 1e-4f);
            float iA = 1.f / (sqrtf(sA) + 1e-4f);
            #pragma unroll
            for (int v = 0; v < NV; v++)
                g_bna[k][h][w][v] = Bc[v] * iB + Ac[v] * iA;
            g_bna[k][h][w][NV] = 0.f;   // pad
        }
    } else {
        // g_ws[k][h][c][o] = conv_w[(k*128 + h*16 + o)*16 + c] * inv[och]
        for (int idx = tid; idx < NK * NC * CG; idx += blockDim.x) {
            int row = idx / CG, c = idx % CG;
            int k = row / NC, och = row % NC;
            float inv = gamma[och] * rsqrtf(var[och] + 1e-5f);
            int h = och / CG, o = och % CG;
            g_ws[k][h][c][o] = conv_w[row * CG + c] * inv;
        }
        for (int och = tid; och < NC; och += blockDim.x) {
            float inv = gamma[och] * rsqrtf(var[och] + 1e-5f);
            float sb = conv_b[och] + conv_b[NC + och] + conv_b[2 * NC + och];
            g_bias[och] = sb * inv + beta[och] - mean[och] * inv;
        }
    }
}

__global__ __launch_bounds__(THREADS, 2)
void blockgcn_main_kernel(const float* __restrict__ x, float* __restrict__ out)
{
    __shared__ __align__(16) float xs[CG][TB][NVP];    // 24576 B
    __shared__ __align__(16) float bnas[NK][NVP][NVP]; //  6912 B  [k][w][v]
    __shared__ __align__(16) float ws_s[NK][CG][CG];   //  3072 B  [k][c][o]
    __shared__ float bias_s[CG];

    const int tile = blockIdx.x;   // 0..15
    const int n    = blockIdx.y;   // 0..31
    const int h    = blockIdx.z;   // 0..7
    const int t0   = tile * TB;
    const int tid  = threadIdx.x;

    // ---- stage x tile (float4 LDG, scalar STS scatter) ----
    const float* xbase = x + ((size_t)(n * NC + h * CG)) * (NT * NV) + (size_t)t0 * NV;
    for (int idx = tid; idx < CG * TB * NV / 4; idx += THREADS) {  // 1472 float4
        int c  = idx / (TB * NV / 4);     // plane of 92 float4
        int r4 = idx % (TB * NV / 4);
        float4 f = ((const float4*)(xbase + (size_t)c * (NT * NV)))[r4];
        int lin = r4 * 4;
        xs[c][lin / NV][lin % NV] = f.x;  lin++;
        xs[c][lin / NV][lin % NV] = f.y;  lin++;
        xs[c][lin / NV][lin % NV] = f.z;  lin++;
        xs[c][lin / NV][lin % NV] = f.w;
    }
    for (int idx = tid; idx < CG * TB; idx += THREADS)
        xs[idx / TB][idx % TB][NV] = 0.f;

    // ---- stage BnA (transposed: [k][w][v]) for this h ----
    for (int idx = tid; idx < NK * NV * NVP; idx += THREADS) {
        int k = idx / (NV * NVP), rem = idx % (NV * NVP);
        bnas[k][rem / NVP][rem % NVP] = (&g_bna[k][h][0][0])[rem];
    }
    // ---- stage folded weights [k][c][o] ----
    for (int idx = tid; idx < NK * CG * CG; idx += THREADS) {
        int k = idx / (CG * CG), rem = idx % (CG * CG);
        (&ws_s[k][0][0])[rem] = (&g_ws[k][h][0][0])[rem];
    }
    if (tid < CG) bias_s[tid] = g_bias[h * CG + tid];
    __syncthreads();

    {
        const int t = tid / NV;
        const int w = tid % NV;

        // init: folded bias + residual, packed over o-pairs
        ull acc2[8];
        #pragma unroll
        for (int op = 0; op < 8; op++)
            acc2[op] = pack2(bias_s[2 * op]     + xs[2 * op][t][w],
                             bias_s[2 * op + 1] + xs[2 * op + 1][t][w]);

        #pragma unroll 1
        for (int k = 0; k < NK; k++) {
            // B column for this lane's w (contiguous row in transposed layout)
            float bcol[NVP];
            {
                const float4* bp = (const float4*)&bnas[k][w][0];
                #pragma unroll
                for (int q = 0; q < 6; q++) {
                    float4 f = bp[q];
                    bcol[4 * q]     = f.x; bcol[4 * q + 1] = f.y;
                    bcol[4 * q + 2] = f.z; bcol[4 * q + 3] = f.w;
                }
            }
            #pragma unroll 4
            for (int c = 0; c < CG; c++) {
                // s = sum_v x[c,t,v] * bcol[v]   (two interleaved chains)
                const float4* xp = (const float4*)&xs[c][t][0];
                float s0 = 0.f, s1 = 0.f;
                #pragma unroll
                for (int q = 0; q < 6; q++) {
                    float4 f = xp[q];
                    s0 = fmaf(f.x, bcol[4 * q],     s0);
                    s1 = fmaf(f.y, bcol[4 * q + 1], s1);
                    s0 = fmaf(f.z, bcol[4 * q + 2], s0);
                    s1 = fmaf(f.w, bcol[4 * q + 3], s1);
                }
                ull s2 = pack2(s0 + s1, s0 + s1);
                // acc2[o-pair] += s * ws[k][c][o]
                const ulonglong2* wp = (const ulonglong2*)&ws_s[k][c][0];
                #pragma unroll
                for (int q = 0; q < 4; q++) {
                    ulonglong2 u = wp[q];
                    acc2[2 * q]     = fma2(s2, u.x, acc2[2 * q]);
                    acc2[2 * q + 1] = fma2(s2, u.y, acc2[2 * q + 1]);
                }
            }
        }

        // epilogue: relu + store
        float* ob = out + ((size_t)(n * NC + h * CG)) * (NT * NV)
                        + (size_t)(t0 + t) * NV + w;
        #pragma unroll
        for (int op = 0; op < 8; op++) {
            float a, b;
            unpack2(acc2[op], a, b);
            ob[(size_t)(2 * op)     * (NT * NV)] = fmaxf(a, 0.f);
            ob[(size_t)(2 * op + 1) * (NT * NV)] = fmaxf(b, 0.f);
        }
    }
}

extern "C" void kernel_launch(void* const* d_in, const int* in_sizes, int n_in,
                              void* d_out, int out_size)
{
    const float* x      = (const float*)d_in[0];
    const float* emb    = (const float*)d_in[1];
    const float* A      = (const float*)d_in[2];
    const float* conv_w = (const float*)d_in[3];
    const float* conv_b = (const float*)d_in[4];
    const float* gamma  = (const float*)d_in[5];
    const float* beta   = (const float*)d_in[6];
    const float* mean   = (const float*)d_in[7];
    const float* var    = (const float*)d_in[8];
    const int*   hop    = (const int*)d_in[9];

    int n_hop = in_sizes[1] / (NK * NH);

    precompute_kernel<<<NK * NH + 1, 256>>>(emb, A, conv_w, conv_b,
                                            gamma, beta, mean, var, hop, n_hop);

    dim3 grid(NT / TB, NN, NH);
    blockgcn_main_kernel<<<grid, THREADS>>>(x, (float*)d_out);
}